// round 3
// baseline (speedup 1.0000x reference)
#include <cuda_runtime.h>

#define BB 4
#define NN 128
#define DD 128
#define EPS 1e-6f

// scratch for x = dense2(glu(dense1(rmsnorm(q))))  : (B, N, 3D) floats
__device__ float g_x[BB * NN * 3 * DD];

// ---------------------------------------------------------------------------
// Phase A: per-row RMSNorm -> GEMM1 (D->2D) -> GLU -> GEMM2 (D->3D) -> g_x
// 4 rows per block, 256 threads. Grid = 512/4 = 128 blocks.
// ---------------------------------------------------------------------------
__global__ __launch_bounds__(256) void phaseA_kernel(
    const float* __restrict__ q,
    const float* __restrict__ norm_w,
    const float* __restrict__ W1,
    const float* __restrict__ b1,
    const float* __restrict__ W2,
    const float* __restrict__ b2)
{
    __shared__ float hs[4][DD];     // normed input, then reused
    __shared__ float ys[4][2 * DD]; // GEMM1 output
    __shared__ float h2s[4][DD];    // GLU output
    __shared__ float rms[4];

    const int tid = threadIdx.x;
    const int row0 = blockIdx.x * 4;   // global row = b*N + n

    // load q rows into smem
    if (tid < DD) {
        #pragma unroll
        for (int r = 0; r < 4; r++)
            hs[r][tid] = q[(row0 + r) * DD + tid];
    }
    __syncthreads();

    // per-row sum of squares (warp r reduces row r)
    const int w = tid >> 5, l = tid & 31;
    if (w < 4) {
        float s = 0.f;
        #pragma unroll
        for (int c = l; c < DD; c += 32) { float v = hs[w][c]; s += v * v; }
        #pragma unroll
        for (int o = 16; o; o >>= 1) s += __shfl_xor_sync(0xffffffffu, s, o);
        if (l == 0) rms[w] = rsqrtf(s * (1.0f / DD) + EPS);
    }
    __syncthreads();

    if (tid < DD) {
        const float nw = 1.0f + norm_w[tid];
        #pragma unroll
        for (int r = 0; r < 4; r++)
            hs[r][tid] *= rms[r] * nw;
    }
    __syncthreads();

    // GEMM1: y[r][o] = b1[o] + sum_d hs[r][d] * W1[o][d]   (o = tid in [0,256))
    {
        const int o = tid;
        float a0 = b1[o], a1 = a0, a2 = a0, a3 = a0;
        const float4* wrow = (const float4*)(W1) + o * (DD / 4);
        const float4* h0 = (const float4*)hs[0];
        const float4* h1 = (const float4*)hs[1];
        const float4* h2 = (const float4*)hs[2];
        const float4* h3 = (const float4*)hs[3];
        #pragma unroll
        for (int d4 = 0; d4 < DD / 4; d4++) {
            float4 wv = __ldg(wrow + d4);
            float4 v;
            v = h0[d4]; a0 += wv.x*v.x + wv.y*v.y + wv.z*v.z + wv.w*v.w;
            v = h1[d4]; a1 += wv.x*v.x + wv.y*v.y + wv.z*v.z + wv.w*v.w;
            v = h2[d4]; a2 += wv.x*v.x + wv.y*v.y + wv.z*v.z + wv.w*v.w;
            v = h3[d4]; a3 += wv.x*v.x + wv.y*v.y + wv.z*v.z + wv.w*v.w;
        }
        ys[0][o] = a0; ys[1][o] = a1; ys[2][o] = a2; ys[3][o] = a3;
    }
    __syncthreads();

    // GLU: h2 = silu(a) * sigmoid(g)
    if (tid < DD) {
        #pragma unroll
        for (int r = 0; r < 4; r++) {
            float a = ys[r][tid];
            float g = ys[r][tid + DD];
            float sa = 1.0f / (1.0f + __expf(-a));
            float sg = 1.0f / (1.0f + __expf(-g));
            h2s[r][tid] = a * sa * sg;
        }
    }
    __syncthreads();

    // GEMM2: x[r][c] = b2[c] + sum_d h2s[r][d] * W2[c][d], c in [0,384)
    for (int c = tid; c < 3 * DD; c += 256) {
        float a0 = b2[c], a1 = a0, a2 = a0, a3 = a0;
        const float4* wrow = (const float4*)(W2) + c * (DD / 4);
        const float4* h0 = (const float4*)h2s[0];
        const float4* h1 = (const float4*)h2s[1];
        const float4* h2 = (const float4*)h2s[2];
        const float4* h3 = (const float4*)h2s[3];
        #pragma unroll
        for (int d4 = 0; d4 < DD / 4; d4++) {
            float4 wv = __ldg(wrow + d4);
            float4 v;
            v = h0[d4]; a0 += wv.x*v.x + wv.y*v.y + wv.z*v.z + wv.w*v.w;
            v = h1[d4]; a1 += wv.x*v.x + wv.y*v.y + wv.z*v.z + wv.w*v.w;
            v = h2[d4]; a2 += wv.x*v.x + wv.y*v.y + wv.z*v.z + wv.w*v.w;
            v = h3[d4]; a3 += wv.x*v.x + wv.y*v.y + wv.z*v.z + wv.w*v.w;
        }
        g_x[(row0 + 0) * 3 * DD + c] = a0;
        g_x[(row0 + 1) * 3 * DD + c] = a1;
        g_x[(row0 + 2) * 3 * DD + c] = a2;
        g_x[(row0 + 3) * 3 * DD + c] = a3;
    }
}

// ---------------------------------------------------------------------------
// Phase B: pairwise accumulation.
// Block = (b, 4 consecutive i). 512 threads = 16 warps:
//   warp w: i_local = w & 3, j-quarter = w >> 2 (32 j each).
//   lane l owns 4 channels (float4) of each 128-channel segment.
// Output: out[0:65536] = q + dq ; out[65536:] = mu + dmu  (B,N,3,D)
// ---------------------------------------------------------------------------
__global__ __launch_bounds__(512) void phaseB_kernel(
    const float* __restrict__ q,
    const float* __restrict__ mu,
    const float* __restrict__ Wij,
    const float* __restrict__ dir_ij,
    const float* __restrict__ mask_ij,
    float* __restrict__ out)
{
    __shared__ float4 psum[16][32][4];   // [warp][lane][accq, am0, am1, am2]

    const int tid = threadIdx.x;
    const int w = tid >> 5, l = tid & 31;
    const int b = blockIdx.x >> 5;            // 32 blocks per batch
    const int i0 = (blockIdx.x & 31) * 4;
    const int il = w & 3;
    const int jq = w >> 2;
    const int i = i0 + il;
    const int bi = b * NN + i;

    float4 accq = make_float4(0.f, 0.f, 0.f, 0.f);
    float4 am0 = accq, am1 = accq, am2 = accq;

    const float*  maskp  = mask_ij + bi * NN;
    const float*  dirp   = dir_ij + bi * NN * 3;
    const float4* Wbase  = (const float4*)Wij + (size_t)bi * NN * 96;
    const float4* xbase  = (const float4*)g_x + b * NN * 96;
    const float4* mubase = (const float4*)mu + b * NN * 96;

    const int jbeg = jq * 32;
    #pragma unroll 2
    for (int j = jbeg; j < jbeg + 32; j++) {
        const float m  = __ldg(maskp + j);
        const float d0 = __ldg(dirp + j * 3 + 0);
        const float d1 = __ldg(dirp + j * 3 + 1);
        const float d2 = __ldg(dirp + j * 3 + 2);

        const float4* Wr = Wbase + j * 96;
        float4 wq = __ldcs(Wr + l);
        float4 wr = __ldcs(Wr + 32 + l);
        float4 wm = __ldcs(Wr + 64 + l);

        const float4* xr_ = xbase + j * 96;
        float4 xq = __ldg(xr_ + l);
        float4 xr = __ldg(xr_ + 32 + l);
        float4 xm = __ldg(xr_ + 64 + l);

        const float4* mur = mubase + j * 96;
        float4 mu0 = __ldg(mur + l);
        float4 mu1 = __ldg(mur + 32 + l);
        float4 mu2 = __ldg(mur + 64 + l);

#define PAINN_COMP(c)                                                   \
        {                                                               \
            accq.c = fmaf(wq.c * xq.c, m, accq.c);                      \
            float t = wr.c * xr.c * m;                                  \
            am0.c = fmaf(t, d0, am0.c);                                 \
            am1.c = fmaf(t, d1, am1.c);                                 \
            am2.c = fmaf(t, d2, am2.c);                                 \
            t = wm.c * xm.c * m;                                        \
            am0.c = fmaf(t, mu0.c, am0.c);                              \
            am1.c = fmaf(t, mu1.c, am1.c);                              \
            am2.c = fmaf(t, mu2.c, am2.c);                              \
        }
        PAINN_COMP(x)
        PAINN_COMP(y)
        PAINN_COMP(z)
        PAINN_COMP(w)
#undef PAINN_COMP
    }

    psum[w][l][0] = accq;
    psum[w][l][1] = am0;
    psum[w][l][2] = am1;
    psum[w][l][3] = am2;
    __syncthreads();

    // warps 0..3 reduce i_local = w over the 4 j-quarters (warps w, w+4, w+8, w+12)
    if (w < 4) {
        float4 r[4];
        #pragma unroll
        for (int t = 0; t < 4; t++) {
            float4 a = psum[w][l][t];
            float4 bq = psum[w + 4][l][t];
            float4 c = psum[w + 8][l][t];
            float4 d = psum[w + 12][l][t];
            r[t].x = a.x + bq.x + c.x + d.x;
            r[t].y = a.y + bq.y + c.y + d.y;
            r[t].z = a.z + bq.z + c.z + d.z;
            r[t].w = a.w + bq.w + c.w + d.w;
        }
        const int bio = b * NN + i0 + w;
        // q output
        const float4 qv = __ldg((const float4*)q + bio * 32 + l);
        float4 oq;
        oq.x = qv.x + r[0].x; oq.y = qv.y + r[0].y;
        oq.z = qv.z + r[0].z; oq.w = qv.w + r[0].w;
        ((float4*)out)[bio * 32 + l] = oq;
        // mu output (offset B*N*D floats)
        float4* omu = (float4*)(out + BB * NN * DD);
        #pragma unroll
        for (int k = 0; k < 3; k++) {
            float4 mv = __ldg((const float4*)mu + bio * 96 + k * 32 + l);
            float4 o4;
            o4.x = mv.x + r[k + 1].x; o4.y = mv.y + r[k + 1].y;
            o4.z = mv.z + r[k + 1].z; o4.w = mv.w + r[k + 1].w;
            omu[bio * 96 + k * 32 + l] = o4;
        }
    }
}

// ---------------------------------------------------------------------------
extern "C" void kernel_launch(void* const* d_in, const int* in_sizes, int n_in,
                              void* d_out, int out_size)
{
    const float* q       = (const float*)d_in[0];
    const float* mu      = (const float*)d_in[1];
    const float* Wij     = (const float*)d_in[2];
    const float* dir_ij  = (const float*)d_in[3];
    const float* mask_ij = (const float*)d_in[4];
    const float* norm_w  = (const float*)d_in[5];
    const float* W1      = (const float*)d_in[6];
    const float* b1      = (const float*)d_in[7];
    const float* W2      = (const float*)d_in[8];
    const float* b2      = (const float*)d_in[9];
    float* out = (float*)d_out;

    phaseA_kernel<<<(BB * NN) / 4, 256>>>(q, norm_w, W1, b1, W2, b2);
    phaseB_kernel<<<(BB * NN) / 4, 512>>>(q, mu, Wij, dir_ij, mask_ij, out);
}

// round 5
// speedup vs baseline: 1.5805x; 1.5805x over previous
#include <cuda_runtime.h>

#define BB 4
#define NN 128
#define DD 128
#define EPS 1e-6f

// scratch for x = dense2(glu(dense1(rmsnorm(q))))  : (B, N, 3D) floats
__device__ float g_x[BB * NN * 3 * DD];

// ---------------------------------------------------------------------------
// Phase A: per-row RMSNorm -> GEMM1 (D->2D) -> GLU -> GEMM2 (D->3D) -> g_x
// Also initializes out with q / mu (phaseB accumulates into out atomically).
// 4 rows per block, 256 threads. Grid = 512/4 = 128 blocks.
// ---------------------------------------------------------------------------
__global__ __launch_bounds__(256) void phaseA_kernel(
    const float* __restrict__ q,
    const float* __restrict__ mu,
    const float* __restrict__ norm_w,
    const float* __restrict__ W1,
    const float* __restrict__ b1,
    const float* __restrict__ W2,
    const float* __restrict__ b2,
    float* __restrict__ out)
{
    __shared__ float hs[4][DD];     // normed input
    __shared__ float ys[4][2 * DD]; // GEMM1 output
    __shared__ float h2s[4][DD];    // GLU output
    __shared__ float rms[4];

    const int tid = threadIdx.x;
    const int row0 = blockIdx.x * 4;   // global row = b*N + n

    // init out with q and mu (phaseB adds dq/dmu via atomics)
    {
        const float4* qs = (const float4*)(q) + row0 * (DD / 4);
        float4* oq = (float4*)(out) + row0 * (DD / 4);
        for (int c = tid; c < 4 * (DD / 4); c += 256) oq[c] = qs[c];
        const float4* ms = (const float4*)(mu) + row0 * (3 * DD / 4);
        float4* om = (float4*)(out + BB * NN * DD) + row0 * (3 * DD / 4);
        for (int c = tid; c < 4 * (3 * DD / 4); c += 256) om[c] = ms[c];
    }

    // load q rows into smem
    if (tid < DD) {
        #pragma unroll
        for (int r = 0; r < 4; r++)
            hs[r][tid] = q[(row0 + r) * DD + tid];
    }
    __syncthreads();

    // per-row sum of squares (warp r reduces row r)
    const int w = tid >> 5, l = tid & 31;
    if (w < 4) {
        float s = 0.f;
        #pragma unroll
        for (int c = l; c < DD; c += 32) { float v = hs[w][c]; s += v * v; }
        #pragma unroll
        for (int o = 16; o; o >>= 1) s += __shfl_xor_sync(0xffffffffu, s, o);
        if (l == 0) rms[w] = rsqrtf(s * (1.0f / DD) + EPS);
    }
    __syncthreads();

    if (tid < DD) {
        const float nw = 1.0f + norm_w[tid];
        #pragma unroll
        for (int r = 0; r < 4; r++)
            hs[r][tid] *= rms[r] * nw;
    }
    __syncthreads();

    // GEMM1: y[r][o] = b1[o] + sum_d hs[r][d] * W1[o][d]   (o = tid in [0,256))
    {
        const int o = tid;
        float a0 = b1[o], a1 = a0, a2 = a0, a3 = a0;
        const float4* wrow = (const float4*)(W1) + o * (DD / 4);
        const float4* h0 = (const float4*)hs[0];
        const float4* h1 = (const float4*)hs[1];
        const float4* h2 = (const float4*)hs[2];
        const float4* h3 = (const float4*)hs[3];
        #pragma unroll
        for (int d4 = 0; d4 < DD / 4; d4++) {
            float4 wv = __ldg(wrow + d4);
            float4 v;
            v = h0[d4]; a0 += wv.x*v.x + wv.y*v.y + wv.z*v.z + wv.w*v.w;
            v = h1[d4]; a1 += wv.x*v.x + wv.y*v.y + wv.z*v.z + wv.w*v.w;
            v = h2[d4]; a2 += wv.x*v.x + wv.y*v.y + wv.z*v.z + wv.w*v.w;
            v = h3[d4]; a3 += wv.x*v.x + wv.y*v.y + wv.z*v.z + wv.w*v.w;
        }
        ys[0][o] = a0; ys[1][o] = a1; ys[2][o] = a2; ys[3][o] = a3;
    }
    __syncthreads();

    // GLU: h2 = silu(a) * sigmoid(g)
    if (tid < DD) {
        #pragma unroll
        for (int r = 0; r < 4; r++) {
            float a = ys[r][tid];
            float g = ys[r][tid + DD];
            float sa = 1.0f / (1.0f + __expf(-a));
            float sg = 1.0f / (1.0f + __expf(-g));
            h2s[r][tid] = a * sa * sg;
        }
    }
    __syncthreads();

    // GEMM2: x[r][c] = b2[c] + sum_d h2s[r][d] * W2[c][d], c in [0,384)
    for (int c = tid; c < 3 * DD; c += 256) {
        float a0 = b2[c], a1 = a0, a2 = a0, a3 = a0;
        const float4* wrow = (const float4*)(W2) + c * (DD / 4);
        const float4* h0 = (const float4*)h2s[0];
        const float4* h1 = (const float4*)h2s[1];
        const float4* h2 = (const float4*)h2s[2];
        const float4* h3 = (const float4*)h2s[3];
        #pragma unroll
        for (int d4 = 0; d4 < DD / 4; d4++) {
            float4 wv = __ldg(wrow + d4);
            float4 v;
            v = h0[d4]; a0 += wv.x*v.x + wv.y*v.y + wv.z*v.z + wv.w*v.w;
            v = h1[d4]; a1 += wv.x*v.x + wv.y*v.y + wv.z*v.z + wv.w*v.w;
            v = h2[d4]; a2 += wv.x*v.x + wv.y*v.y + wv.z*v.z + wv.w*v.w;
            v = h3[d4]; a3 += wv.x*v.x + wv.y*v.y + wv.z*v.z + wv.w*v.w;
        }
        g_x[(row0 + 0) * 3 * DD + c] = a0;
        g_x[(row0 + 1) * 3 * DD + c] = a1;
        g_x[(row0 + 2) * 3 * DD + c] = a2;
        g_x[(row0 + 3) * 3 * DD + c] = a3;
    }
}

// ---------------------------------------------------------------------------
// Phase B: pairwise accumulation, occupancy-optimized.
// Block = (b, 4-i tile, 32-j tile). 256 threads = 8 warps:
//   warp w: i_local = w & 3, j-half = w >> 2 (16 j each).
//   lane l owns 4 channels (float4) of each 128-channel segment.
// Grid = 4 * 32 * 4 = 512 blocks, 3 blocks/SM (launch_bounds-forced).
// Cross-block (j-tile) reduction via atomicAdd into out (pre-initialized
// with q/mu by phaseA).
// ---------------------------------------------------------------------------
__global__ __launch_bounds__(256, 3) void phaseB_kernel(
    const float* __restrict__ mu,
    const float* __restrict__ Wij,
    const float* __restrict__ dir_ij,
    const float* __restrict__ mask_ij,
    float* __restrict__ out)
{
    __shared__ float4 psum[8][32][4];   // [warp][lane][accq, am0, am1, am2]

    const int tid = threadIdx.x;
    const int w = tid >> 5, l = tid & 31;
    const int jt = blockIdx.x & 3;            // j-tile (32 j)
    const int it = (blockIdx.x >> 2) & 31;    // i-tile (4 i)
    const int b  = blockIdx.x >> 7;
    const int il = w & 3;
    const int jh = w >> 2;                    // j-half within tile (16 j)
    const int i = it * 4 + il;
    const int bi = b * NN + i;

    float4 accq = make_float4(0.f, 0.f, 0.f, 0.f);
    float4 am0 = accq, am1 = accq, am2 = accq;

    const float*  maskp  = mask_ij + bi * NN;
    const float*  dirp   = dir_ij + bi * NN * 3;
    const float4* Wbase  = (const float4*)Wij + (size_t)bi * NN * 96;
    const float4* xbase  = (const float4*)g_x + b * NN * 96;
    const float4* mubase = (const float4*)mu + b * NN * 96;

    const int jbeg = jt * 32 + jh * 16;
    #pragma unroll 2
    for (int j = jbeg; j < jbeg + 16; j++) {
        const float m  = __ldg(maskp + j);
        const float d0 = __ldg(dirp + j * 3 + 0);
        const float d1 = __ldg(dirp + j * 3 + 1);
        const float d2 = __ldg(dirp + j * 3 + 2);

        const float4* Wr = Wbase + j * 96;
        float4 wq = __ldcs(Wr + l);
        float4 wr = __ldcs(Wr + 32 + l);
        float4 wm = __ldcs(Wr + 64 + l);

        const float4* xr_ = xbase + j * 96;
        float4 xq = __ldg(xr_ + l);
        float4 xr = __ldg(xr_ + 32 + l);
        float4 xm = __ldg(xr_ + 64 + l);

        const float4* mur = mubase + j * 96;
        float4 mu0 = __ldg(mur + l);
        float4 mu1 = __ldg(mur + 32 + l);
        float4 mu2 = __ldg(mur + 64 + l);

#define PAINN_COMP(c)                                                   \
        {                                                               \
            accq.c = fmaf(wq.c * xq.c, m, accq.c);                      \
            float t = wr.c * xr.c * m;                                  \
            am0.c = fmaf(t, d0, am0.c);                                 \
            am1.c = fmaf(t, d1, am1.c);                                 \
            am2.c = fmaf(t, d2, am2.c);                                 \
            t = wm.c * xm.c * m;                                        \
            am0.c = fmaf(t, mu0.c, am0.c);                              \
            am1.c = fmaf(t, mu1.c, am1.c);                              \
            am2.c = fmaf(t, mu2.c, am2.c);                              \
        }
        PAINN_COMP(x)
        PAINN_COMP(y)
        PAINN_COMP(z)
        PAINN_COMP(w)
#undef PAINN_COMP
    }

    psum[w][l][0] = accq;
    psum[w][l][1] = am0;
    psum[w][l][2] = am1;
    psum[w][l][3] = am2;
    __syncthreads();

    // warps 0..3 reduce i_local = w over the 2 j-halves, then atomicAdd.
    if (w < 4) {
        float4 r[4];
        #pragma unroll
        for (int t = 0; t < 4; t++) {
            float4 a = psum[w][l][t];
            float4 c = psum[w + 4][l][t];
            r[t].x = a.x + c.x;
            r[t].y = a.y + c.y;
            r[t].z = a.z + c.z;
            r[t].w = a.w + c.w;
        }
        const int bio = b * NN + it * 4 + w;
        // q output: out[bio*D + 4l ..]
        float* oq = out + bio * DD + 4 * l;
        atomicAdd(oq + 0, r[0].x);
        atomicAdd(oq + 1, r[0].y);
        atomicAdd(oq + 2, r[0].z);
        atomicAdd(oq + 3, r[0].w);
        // mu output (offset B*N*D floats), (B,N,3,D)
        float* om = out + BB * NN * DD + bio * 3 * DD + 4 * l;
        #pragma unroll
        for (int k = 0; k < 3; k++) {
            atomicAdd(om + k * DD + 0, r[k + 1].x);
            atomicAdd(om + k * DD + 1, r[k + 1].y);
            atomicAdd(om + k * DD + 2, r[k + 1].z);
            atomicAdd(om + k * DD + 3, r[k + 1].w);
        }
    }
}

// ---------------------------------------------------------------------------
extern "C" void kernel_launch(void* const* d_in, const int* in_sizes, int n_in,
                              void* d_out, int out_size)
{
    const float* q       = (const float*)d_in[0];
    const float* mu      = (const float*)d_in[1];
    const float* Wij     = (const float*)d_in[2];
    const float* dir_ij  = (const float*)d_in[3];
    const float* mask_ij = (const float*)d_in[4];
    const float* norm_w  = (const float*)d_in[5];
    const float* W1      = (const float*)d_in[6];
    const float* b1      = (const float*)d_in[7];
    const float* W2      = (const float*)d_in[8];
    const float* b2      = (const float*)d_in[9];
    float* out = (float*)d_out;

    phaseA_kernel<<<(BB * NN) / 4, 256>>>(q, mu, norm_w, W1, b1, W2, b2, out);
    phaseB_kernel<<<BB * NN, 256>>>(mu, Wij, dir_ij, mask_ij, out);
}